// round 15
// baseline (speedup 1.0000x reference)
#include <cuda_runtime.h>
#include <cuda_fp16.h>
#include <cstdint>
#include <cstddef>

#define N_NODES 12288
#define F 128
#define BM 128
#define BK 64
#define KSPLIT 12
#define KLEN (N_NODES / KSPLIT)     // 1024
#define KSTAGES (KLEN / BK)         // 16
#define TILES_M (N_NODES / BM)      // 96
#define GRID (TILES_M * KSPLIT)     // 1152
#define THREADS 512

#define A_BYTES (BM * 128)          // 16384 per A plane
#define ST_A2   (2 * A_BYTES)       // 32768: [sign][edge]
#define B_BYTES (128 * 128)         // 16384
#define STAGE_BYTES (ST_A2 + B_BYTES)   // 49152
#define SM_MAIN (2 * STAGE_BYTES)       // 98304
#define STG_NODE SM_MAIN                // raw fp32 adjacency staging (32KB)
#define STG_EDGE (SM_MAIN + 32768)      // 32KB
#define SMEM_TOTAL (SM_MAIN + 65536)    // 163840

#define FH (F / 2)                      // 64 uints per row (fp16 pairs)
#define PLANE_H ((size_t)N_NODES * FH)
#define SLICE_H (2 * PLANE_H)

// Scratch: fp16 partial planes (75.5 MB), fp16 featsT tiles, folded W
__device__ uint32_t g_S[(size_t)KSPLIT * 2 * N_NODES * FH];
__device__ uint4 g_fB[(size_t)(N_NODES / BK) * B_BYTES / 16];
__device__ float g_cpart[96 * F];
__device__ float g_Wd[F * F];
__device__ float g_b2[F];

// ---------------------------------------------------------------------------
// helpers
// ---------------------------------------------------------------------------
__device__ __forceinline__ uint32_t smem_u32(const void* p) {
    uint32_t a;
    asm("{ .reg .u64 t; cvta.to.shared.u64 t, %1; cvt.u32.u64 %0, t; }"
        : "=r"(a) : "l"(p));
    return a;
}

__device__ __forceinline__ uint32_t pack_h2(float lo, float hi) {
    __half2 h = __floats2half2_rn(lo, hi);
    return *(uint32_t*)&h;
}

__device__ __forceinline__ float sgnf(float v) {
    return (v > 0.f ? 1.f : 0.f) - (v < 0.f ? 1.f : 0.f);
}

#define SWX(off) ((off) ^ (((off) >> 3) & 0x70))
#define SSTG(t, q) ((uint32_t)(((t) * 64 + (q) * 16) ^ (((t) & 6) << 3)))

#define CP_ASYNC16(dst_u32, src) \
    asm volatile("cp.async.cg.shared.global [%0], [%1], 16;" \
                 :: "r"(dst_u32), "l"(src) : "memory")
#define CP_COMMIT() asm volatile("cp.async.commit_group;" ::: "memory")
#define CP_WAIT0()  asm volatile("cp.async.wait_group 0;" ::: "memory")
#define CP_WAIT1()  asm volatile("cp.async.wait_group 1;" ::: "memory")

#define LDS128F(v, addr) \
    asm volatile("ld.shared.v4.f32 {%0,%1,%2,%3}, [%4];" \
                 : "=f"((v).x), "=f"((v).y), "=f"((v).z), "=f"((v).w) : "r"(addr))

#define LDSM_X4(r0, r1, r2, r3, addr) \
    asm volatile("ldmatrix.sync.aligned.m8n8.x4.shared.b16 {%0,%1,%2,%3}, [%4];" \
                 : "=r"(r0), "=r"(r1), "=r"(r2), "=r"(r3) : "r"(addr))

__device__ __forceinline__ void mma_f16(float* d, const uint32_t* a,
                                        uint32_t b0, uint32_t b1) {
    asm volatile(
        "mma.sync.aligned.m16n8k16.row.col.f32.f16.f16.f32 "
        "{%0,%1,%2,%3}, {%4,%5,%6,%7}, {%8,%9}, {%0,%1,%2,%3};\n"
        : "+f"(d[0]), "+f"(d[1]), "+f"(d[2]), "+f"(d[3])
        : "r"(a[0]), "r"(a[1]), "r"(a[2]), "r"(a[3]), "r"(b0), "r"(b1));
}

// ---------------------------------------------------------------------------
// Prepass kernels
// ---------------------------------------------------------------------------
__global__ __launch_bounds__(128)
void colsum_kernel(const float* __restrict__ feats) {
    const int t = threadIdx.x;
    const int r0 = blockIdx.x * 128;
    float s = 0.f;
#pragma unroll 4
    for (int r = 0; r < 128; ++r)
        s += feats[(size_t)(r0 + r) * F + t];
    g_cpart[blockIdx.x * F + t] = s;
}

__global__ __launch_bounds__(128)
void wtrans_kernel(const float* __restrict__ node_weight,
                   const float* __restrict__ node_bias) {
    __shared__ float cs[F];
    const int j = threadIdx.x;
    {
        float c = 0.f;
#pragma unroll 4
        for (int b = 0; b < 96; ++b)
            c += g_cpart[b * F + j];
        cs[j] = c;
    }
    __syncthreads();
    float b = node_bias[j];
#pragma unroll 4
    for (int k = 0; k < 128; ++k) {
        const float wt = node_weight[(size_t)k * F + j];
        const float wb = node_weight[(size_t)(k + 128) * F + j];
        g_Wd[k * F + j] = 0.5f * (wt - wb);
        b += cs[k] * 0.5f * (wt + wb);
    }
    g_b2[j] = b;
}

__global__ __launch_bounds__(256)
void prep_feats(const float* __restrict__ feats) {
    const int s = blockIdx.x;
    const int t = threadIdx.x;
    const int n = t >> 1;
    const int kh = (t & 1) * 32;
    const int jb = blockIdx.y * 8;
    uint32_t* out = (uint32_t*)g_fB + (size_t)s * (B_BYTES / 4);
    const float* src = feats + (size_t)(s * BK + kh) * F + n;
#pragma unroll
    for (int j = jb; j < jb + 8; j += 2) {
        const float v0 = src[(size_t)j * F];
        const float v1 = src[(size_t)(j + 1) * F];
        const uint32_t off = (uint32_t)(n * 128 + (kh + j) * 2);
        out[SWX(off) >> 2] = pack_h2(v0, v1);
    }
}

// ---------------------------------------------------------------------------
// Main kernel: split-K x12, BM=128, 16 warps (8m x 2n), 512 threads.
// Group-wise cp.async waits keep B-copy latency off the convert path.
// ---------------------------------------------------------------------------
__global__ __launch_bounds__(THREADS, 1)
void spmm2_f16(const float* __restrict__ node_adj,
               const float* __restrict__ edge_adj) {
    extern __shared__ char smem[];
    const uint32_t sb = smem_u32(smem);
    const int tid  = threadIdx.x;
    const int wid  = tid >> 5;
    const int lane = tid & 31;
    const int M0     = (blockIdx.x % TILES_M) * BM;
    const int kslice = blockIdx.x / TILES_M;
    const size_t K0  = (size_t)kslice * KLEN;

    // ---- converter mapping ----
    const int cm = tid >> 2;
    const int kq = tid & 3;
    const float* nrow = node_adj + (size_t)(M0 + cm) * N_NODES + K0 + kq * 16;
    const float* erow = edge_adj + (size_t)(M0 + cm) * N_NODES + K0 + kq * 16;
    const uint32_t csts0 = SWX((uint32_t)(cm * 128 + kq * 32));
    const uint32_t csts1 = SWX((uint32_t)(cm * 128 + kq * 32 + 16));
    uint32_t stgNq[4], stgEq[4];
#pragma unroll
    for (int q = 0; q < 4; ++q) {
        stgNq[q] = sb + STG_NODE + SSTG(tid, q);
        stgEq[q] = sb + STG_EDGE + SSTG(tid, q);
    }

    // ---- mma mapping: 8m x 2n warps ----
    const int wm = (wid & 7) * 16;
    const int wn = (wid >> 3) * 64;
    const uint32_t arow = wm + (lane & 15);
    const uint32_t abase = arow * 128 + (lane >> 4) * 16;
    const uint32_t axor = (arow & 7) << 4;
    uint32_t bbase[4], bxor[4];
#pragma unroll
    for (int np = 0; np < 4; ++np) {
        const uint32_t brow = wn + np * 16 + ((lane >> 4) << 3) + (lane & 7);
        bbase[np] = brow * 128 + ((lane >> 3) & 1) * 16;
        bxor[np]  = (brow & 7) << 4;
    }

    float acc[2][8][4];
#pragma unroll
    for (int p = 0; p < 2; ++p)
#pragma unroll
        for (int nt = 0; nt < 8; ++nt)
#pragma unroll
            for (int c = 0; c < 4; ++c) acc[p][nt][c] = 0.f;

    const char* fB = (const char*)g_fB + (size_t)(kslice * KSTAGES) * B_BYTES;

    auto stage_adj = [&](int s) {
        const size_t k0 = (size_t)s * BK;
#pragma unroll
        for (int q = 0; q < 4; ++q) {
            CP_ASYNC16(stgNq[q], nrow + k0 + q * 4);
            CP_ASYNC16(stgEq[q], erow + k0 + q * 4);
        }
    };
    auto stage_B = [&](int s, uint32_t buf_off) {
        const uint32_t dst = sb + buf_off + ST_A2 + tid * 32;
        const char* src = fB + (size_t)s * B_BYTES + tid * 32;
        CP_ASYNC16(dst, src);
        CP_ASYNC16(dst + 16, src + 16);
    };
    auto convert = [&](uint32_t dbuf_off) {
        char* bp = smem + dbuf_off;
        {
            float4 n0, n1, n2, n3;
            LDS128F(n0, stgNq[0]); LDS128F(n1, stgNq[1]);
            LDS128F(n2, stgNq[2]); LDS128F(n3, stgNq[3]);
            uint4 S0, S1;
            S0 = make_uint4(pack_h2(sgnf(n0.x), sgnf(n0.y)), pack_h2(sgnf(n0.z), sgnf(n0.w)),
                            pack_h2(sgnf(n1.x), sgnf(n1.y)), pack_h2(sgnf(n1.z), sgnf(n1.w)));
            S1 = make_uint4(pack_h2(sgnf(n2.x), sgnf(n2.y)), pack_h2(sgnf(n2.z), sgnf(n2.w)),
                            pack_h2(sgnf(n3.x), sgnf(n3.y)), pack_h2(sgnf(n3.z), sgnf(n3.w)));
            *(uint4*)(bp + 0 * A_BYTES + csts0) = S0;
            *(uint4*)(bp + 0 * A_BYTES + csts1) = S1;
        }
        {
            float4 e0, e1, e2, e3;
            LDS128F(e0, stgEq[0]); LDS128F(e1, stgEq[1]);
            LDS128F(e2, stgEq[2]); LDS128F(e3, stgEq[3]);
            uint4 E0, E1;
            E0 = make_uint4(pack_h2(e0.x, e0.y), pack_h2(e0.z, e0.w),
                            pack_h2(e1.x, e1.y), pack_h2(e1.z, e1.w));
            E1 = make_uint4(pack_h2(e2.x, e2.y), pack_h2(e2.z, e2.w),
                            pack_h2(e3.x, e3.y), pack_h2(e3.z, e3.w));
            *(uint4*)(bp + 1 * A_BYTES + csts0) = E0;
            *(uint4*)(bp + 1 * A_BYTES + csts1) = E1;
        }
    };

    // ---- prologue ----
    stage_B(0, 0);
    stage_adj(0);
    CP_COMMIT();                  // G: B0+adj0
    CP_WAIT0();
    convert(0);
    stage_adj(1);
    CP_COMMIT();                  // G: adj1
    __syncthreads();

#pragma unroll 1
    for (int s = 0; s < KSTAGES; ++s) {
        const uint32_t cur = (uint32_t)(s & 1) * STAGE_BYTES;
        const uint32_t nxt = (uint32_t)((s + 1) & 1) * STAGE_BYTES;

        // (a) B copy for stage s+1 (own group; drained after convert below)
        if (s + 1 < KSTAGES) {
            stage_B(s + 1, nxt);
            CP_COMMIT();          // pending: {adj(s+1), B(s+1)}
        }

        // (b) compute stage s
        const uint32_t sbA = sb + cur;
        const uint32_t sbB = sb + cur + ST_A2;
#pragma unroll
        for (int ks = 0; ks < 4; ++ks) {
            uint32_t b[4][4];
#pragma unroll
            for (int np = 0; np < 4; ++np)
                LDSM_X4(b[np][0], b[np][1], b[np][2], b[np][3],
                        sbB + ((bbase[np] + ks * 32) ^ bxor[np]));
#pragma unroll
            for (int p = 0; p < 2; ++p) {
                uint32_t a[4];
                LDSM_X4(a[0], a[1], a[2], a[3],
                        sbA + p * A_BYTES + ((abase + ks * 32) ^ axor));
#pragma unroll
                for (int np = 0; np < 4; ++np) {
                    mma_f16(acc[p][np * 2],     a, b[np][0], b[np][1]);
                    mma_f16(acc[p][np * 2 + 1], a, b[np][2], b[np][3]);
                }
            }
        }

        // (c) wait adjacency group only; convert; refill staging; drain B
        if (s + 1 < KSTAGES) {
            CP_WAIT1();           // adj(s+1) landed; B(s+1) may still fly
            convert(nxt);
            if (s + 2 < KSTAGES) {
                stage_adj(s + 2);
                CP_COMMIT();      // pending: {B(s+1), adj(s+2)}
                CP_WAIT1();       // B(s+1) landed
            } else {
                CP_WAIT0();       // drain B(s+1)
            }
            __syncthreads();
        }
    }

    // ---- epilogue: write fp16 partial planes for this k-slice ----
    const int er0 = wm + (lane >> 2);
    const int ec0 = wn + (lane & 3) * 2;
#pragma unroll
    for (int p = 0; p < 2; ++p) {
        uint32_t* base = g_S + (size_t)kslice * SLICE_H + (size_t)p * PLANE_H
                       + (size_t)(M0 + er0) * FH + (ec0 >> 1);
#pragma unroll
        for (int nt = 0; nt < 8; ++nt) {
            base[nt * 4]          = pack_h2(acc[p][nt][0], acc[p][nt][1]);
            base[8 * FH + nt * 4] = pack_h2(acc[p][nt][2], acc[p][nt][3]);
        }
    }
}

// ---------------------------------------------------------------------------
// Combine: 64 rows/block, per-thread 4 contiguous cols (float4 LDS/STG).
// out = relu(sum Ssign@Wd + b2) + sum Sedge@We + eb
// ---------------------------------------------------------------------------
__device__ __forceinline__ void accum_block(const float* __restrict__ W,
                                            const uint32_t* __restrict__ S,
                                            float* acc,             // [8][4]
                                            float* Ws, float* Ss,
                                            int tid, int tx, int ty, int R0) {
#pragma unroll 1
    for (int k0 = 0; k0 < 128; k0 += 32) {
        __syncthreads();
        // W tile 32x128 (1024 float4, 256 threads x 4)
#pragma unroll
        for (int i = 0; i < 4; ++i) {
            const int e = tid + i * 256;
            const int wrow = e >> 5;
            const int wc = (e & 31) * 4;
            *(float4*)(Ws + wrow * 128 + wc) = *(const float4*)(W + (k0 + wrow) * 128 + wc);
        }
        // S tile 64x32: thread handles row srow, 8 cols (sc..sc+7), 12-slice sum
        {
            const int srow = tid >> 2;          // 0..63
            const int sc = (tid & 3) * 8;       // 0,8,16,24
            const uint32_t* Sh = S + (size_t)(R0 + srow) * FH + ((k0 + sc) >> 1);
            float4 t0 = make_float4(0.f, 0.f, 0.f, 0.f);
            float4 t1 = make_float4(0.f, 0.f, 0.f, 0.f);
#pragma unroll
            for (int sl = 0; sl < KSPLIT; ++sl) {
                const uint4 v = *(const uint4*)(Sh + (size_t)sl * SLICE_H);
                const float2 a0 = __half22float2(*(const __half2*)&v.x);
                const float2 a1 = __half22float2(*(const __half2*)&v.y);
                const float2 a2 = __half22float2(*(const __half2*)&v.z);
                const float2 a3 = __half22float2(*(const __half2*)&v.w);
                t0.x += a0.x; t0.y += a0.y; t0.z += a1.x; t0.w += a1.y;
                t1.x += a2.x; t1.y += a2.y; t1.z += a3.x; t1.w += a3.y;
            }
            *(float4*)(Ss + srow * 36 + sc)     = t0;
            *(float4*)(Ss + srow * 36 + sc + 4) = t1;
        }
        __syncthreads();
#pragma unroll 8
        for (int kk = 0; kk < 32; ++kk) {
            const float4 w4 = *(const float4*)(Ws + kk * 128 + tx * 4);
            float sv[8];
#pragma unroll
            for (int u = 0; u < 8; ++u) sv[u] = Ss[(ty + 8 * u) * 36 + kk];
#pragma unroll
            for (int u = 0; u < 8; ++u) {
                acc[u * 4 + 0] = fmaf(sv[u], w4.x, acc[u * 4 + 0]);
                acc[u * 4 + 1] = fmaf(sv[u], w4.y, acc[u * 4 + 1]);
                acc[u * 4 + 2] = fmaf(sv[u], w4.z, acc[u * 4 + 2]);
                acc[u * 4 + 3] = fmaf(sv[u], w4.w, acc[u * 4 + 3]);
            }
        }
    }
}

__global__ __launch_bounds__(256)
void combine_kernel(const float* __restrict__ edge_weight,
                    const float* __restrict__ edge_bias,
                    float* __restrict__ out) {
    __shared__ float Ws[32 * 128];
    __shared__ float Ss[64 * 36];

    const int tid = threadIdx.x;
    const int tx = tid & 31;          // col group: cols tx*4..tx*4+3
    const int ty = tid >> 5;          // 0..7; rows ty+8u, u<8
    const int R0 = blockIdx.x * 64;

    float accN[32], accE[32];
#pragma unroll
    for (int i = 0; i < 32; ++i) { accN[i] = 0.f; accE[i] = 0.f; }

    accum_block(g_Wd,        g_S,           accN, Ws, Ss, tid, tx, ty, R0);
    accum_block(edge_weight, g_S + PLANE_H, accE, Ws, Ss, tid, tx, ty, R0);

    const float4 b2 = *(const float4*)(g_b2 + tx * 4);
    const float4 eb = *(const float4*)(edge_bias + tx * 4);
#pragma unroll
    for (int u = 0; u < 8; ++u) {
        const int rr = R0 + ty + 8 * u;
        float4 o;
        o.x = fmaxf(accN[u * 4 + 0] + b2.x, 0.f) + accE[u * 4 + 0] + eb.x;
        o.y = fmaxf(accN[u * 4 + 1] + b2.y, 0.f) + accE[u * 4 + 1] + eb.y;
        o.z = fmaxf(accN[u * 4 + 2] + b2.z, 0.f) + accE[u * 4 + 2] + eb.z;
        o.w = fmaxf(accN[u * 4 + 3] + b2.w, 0.f) + accE[u * 4 + 3] + eb.w;
        *(float4*)(out + (size_t)rr * F + tx * 4) = o;
    }
}

extern "C" void kernel_launch(void* const* d_in, const int* in_sizes, int n_in,
                              void* d_out, int out_size) {
    const float* feats       = (const float*)d_in[0];
    const float* node_adj    = (const float*)d_in[1];
    const float* edge_adj    = (const float*)d_in[2];
    const float* node_weight = (const float*)d_in[3];
    const float* node_bias   = (const float*)d_in[4];
    const float* edge_weight = (const float*)d_in[5];
    const float* edge_bias   = (const float*)d_in[6];
    float* out = (float*)d_out;

    cudaFuncSetAttribute(spmm2_f16, cudaFuncAttributeMaxDynamicSharedMemorySize, SMEM_TOTAL);

    colsum_kernel<<<96, 128>>>(feats);
    wtrans_kernel<<<1, 128>>>(node_weight, node_bias);
    prep_feats<<<dim3(N_NODES / BK, 4), 256>>>(feats);
    spmm2_f16<<<GRID, THREADS, SMEM_TOTAL>>>(node_adj, edge_adj);
    combine_kernel<<<N_NODES / 64, 256>>>(edge_weight, edge_bias, out);
}